// round 1
// baseline (speedup 1.0000x reference)
#include <cuda_runtime.h>

#define NB 16384
#define HD 768

// ---------------- scratch (device globals; no allocs allowed) ----------------
__device__ float g_scrA[NB * 768];   // 48 MB
__device__ float g_scrB[NB * 384];   // 24 MB
__device__ float g_scrC[NB * 256];   // 16 MB
__device__ float g_scrD[NB * 64];    //  4 MB
__device__ float g_norm[2 * NB];     // norms of image_feat, text_feat

// ---------------- helpers ----------------
__device__ __forceinline__ float sigf(float x) { return 1.0f / (1.0f + expf(-x)); }
__device__ __forceinline__ float geluf(float x) { return 0.5f * x * (1.0f + erff(x * 0.70710678118654752f)); }

__device__ __forceinline__ unsigned long long pack2b(float x) {
    unsigned long long r;
    asm("mov.b64 %0, {%1, %1};" : "=l"(r) : "f"(x));
    return r;
}
__device__ __forceinline__ void unpack2(unsigned long long v, float& x, float& y) {
    asm("mov.b64 {%0, %1}, %2;" : "=f"(x), "=f"(y) : "l"(v));
}
__device__ __forceinline__ void ffma2(unsigned long long& d, unsigned long long a, unsigned long long b) {
    asm("fma.rn.f32x2 %0, %1, %2, %0;" : "+l"(d) : "l"(a), "l"(b));
}

// ---------------- GEMM: C[M,N] = act(A @ W + bias) ----------------
// A given as two halves (concat support): row stride Khalf each.
// BM=128, BN=64, BK=16, 256 threads, thread tile 8(M as 4 f32x2 pairs) x 4(N).
__global__ __launch_bounds__(256) void gemm_k(
    const float* __restrict__ A1, const float* __restrict__ A2,
    int Khalf, int Ktot,
    const float* __restrict__ W, int N,
    const float* __restrict__ bias,
    float* __restrict__ C, int act)
{
    __shared__ float As[16 * 130];
    __shared__ float Bs[16 * 64];
    const int t  = threadIdx.x;
    const int tx = t & 15;        // N groups of 4
    const int ty = t >> 4;        // M groups of 8
    const int n0 = blockIdx.x * 64;
    const int m0 = blockIdx.y * 128;

    unsigned long long acc[4][4];
#pragma unroll
    for (int i = 0; i < 4; i++)
#pragma unroll
        for (int j = 0; j < 4; j++) acc[i][j] = 0ull;

    for (int k0 = 0; k0 < Ktot; k0 += 16) {
        const float* Abase;
        int kk;
        if (k0 < Khalf) { Abase = A1; kk = k0; }
        else            { Abase = A2; kk = k0 - Khalf; }

        // load A tile [128 x 16] -> As transposed [16][130]
#pragma unroll
        for (int l = 0; l < 2; l++) {
            int idx = t + l * 256;      // 0..511
            int r   = idx >> 2;         // row 0..127
            int c4  = (idx & 3) * 4;    // col 0,4,8,12
            float4 v = *reinterpret_cast<const float4*>(Abase + (size_t)(m0 + r) * Khalf + kk + c4);
            As[(c4 + 0) * 130 + r] = v.x;
            As[(c4 + 1) * 130 + r] = v.y;
            As[(c4 + 2) * 130 + r] = v.z;
            As[(c4 + 3) * 130 + r] = v.w;
        }
        // load B tile [16 x 64]
        {
            int r = t >> 4;
            int c = (t & 15) * 4;
            float4 v = *reinterpret_cast<const float4*>(W + (size_t)(k0 + r) * N + n0 + c);
            *reinterpret_cast<float4*>(&Bs[r * 64 + c]) = v;
        }
        __syncthreads();

#pragma unroll
        for (int k = 0; k < 16; k++) {
            unsigned long long a2[4];
            const unsigned long long* pA =
                reinterpret_cast<const unsigned long long*>(&As[k * 130 + ty * 8]);
            a2[0] = pA[0]; a2[1] = pA[1]; a2[2] = pA[2]; a2[3] = pA[3];
            float4 bv = *reinterpret_cast<const float4*>(&Bs[k * 64 + tx * 4]);
            unsigned long long b2[4];
            b2[0] = pack2b(bv.x); b2[1] = pack2b(bv.y);
            b2[2] = pack2b(bv.z); b2[3] = pack2b(bv.w);
#pragma unroll
            for (int i = 0; i < 4; i++)
#pragma unroll
                for (int j = 0; j < 4; j++) ffma2(acc[i][j], a2[i], b2[j]);
        }
        __syncthreads();
    }

    // epilogue
    float bb[4];
#pragma unroll
    for (int j = 0; j < 4; j++) bb[j] = bias[n0 + tx * 4 + j];

#pragma unroll
    for (int i = 0; i < 4; i++) {
        int m = m0 + ty * 8 + i * 2;
        float lo[4], hi[4];
#pragma unroll
        for (int j = 0; j < 4; j++) {
            unpack2(acc[i][j], lo[j], hi[j]);
            lo[j] += bb[j];
            hi[j] += bb[j];
            if (act == 1) { lo[j] = geluf(lo[j]); hi[j] = geluf(hi[j]); }
        }
        float4 r0 = make_float4(lo[0], lo[1], lo[2], lo[3]);
        float4 r1 = make_float4(hi[0], hi[1], hi[2], hi[3]);
        *reinterpret_cast<float4*>(C + (size_t)m * N + n0 + tx * 4)       = r0;
        *reinterpret_cast<float4*>(C + (size_t)(m + 1) * N + n0 + tx * 4) = r1;
    }
}

// ---------------- final dot head: out[m] = sigmoid(H[m,:] . w + b) ----------------
__global__ void dot_head_k(const float* __restrict__ Hin, int K,
                           const float* __restrict__ w, const float* __restrict__ b,
                           float* __restrict__ outrow)
{
    int gw   = (blockIdx.x * blockDim.x + threadIdx.x) >> 5;
    int lane = threadIdx.x & 31;
    if (gw >= NB) return;
    const float* row = Hin + (size_t)gw * K;
    float s = 0.f;
    for (int k = lane * 4; k < K; k += 128) {
        float4 v  = *reinterpret_cast<const float4*>(row + k);
        float4 wv = *reinterpret_cast<const float4*>(w + k);
        s += v.x * wv.x + v.y * wv.y + v.z * wv.z + v.w * wv.w;
    }
#pragma unroll
    for (int o = 16; o; o >>= 1) s += __shfl_xor_sync(0xffffffffu, s, o);
    if (lane == 0) outrow[gw] = sigf(s + b[0]);
}

// ---------------- geometric quality (rows 0..3) + norms ----------------
__global__ void rowstats_k(const float* __restrict__ f0, const float* __restrict__ f1,
                           const float* __restrict__ f2, const float* __restrict__ f3,
                           float* __restrict__ out)
{
    int gw   = (blockIdx.x * blockDim.x + threadIdx.x) >> 5;
    int lane = threadIdx.x & 31;
    if (gw >= 4 * NB) return;
    int feat = gw >> 14;
    int m    = gw & (NB - 1);
    const float* f = (feat == 0 ? f0 : feat == 1 ? f1 : feat == 2 ? f2 : f3) + (size_t)m * HD;

    double sum = 0.0, ssq = 0.0;
    int cnt = 0;
    for (int k = lane * 4; k < HD; k += 128) {
        float4 v = *reinterpret_cast<const float4*>(f + k);
        sum += (double)v.x + v.y + v.z + v.w;
        ssq += (double)v.x * v.x + (double)v.y * v.y + (double)v.z * v.z + (double)v.w * v.w;
        cnt += (fabsf(v.x) > 0.01f) + (fabsf(v.y) > 0.01f) + (fabsf(v.z) > 0.01f) + (fabsf(v.w) > 0.01f);
    }
#pragma unroll
    for (int o = 16; o; o >>= 1) {
        sum += __shfl_xor_sync(0xffffffffu, sum, o);
        ssq += __shfl_xor_sync(0xffffffffu, ssq, o);
        cnt += __shfl_xor_sync(0xffffffffu, cnt, o);
    }
    if (lane == 0) {
        float n   = (float)sqrt(ssq);
        float nq  = sigf((n - 1.0f) * 2.0f);
        float sp  = cnt * (1.0f / 768.0f);
        double var = (ssq - sum * sum / 768.0) / 767.0;
        if (var < 0.0) var = 0.0;
        float sq  = sigf((float)sqrt(var) * 10.0f - 1.0f);
        out[feat * NB + m] = (nq + sp + sq) * (1.0f / 3.0f);
        if (feat < 2) g_norm[feat * NB + m] = n;
    }
}

// ---------------- information quality final (entropy etc.) ----------------
__global__ void info_final_k(const float* __restrict__ enc, int fi, float* __restrict__ outrow)
{
    int gw   = (blockIdx.x * blockDim.x + threadIdx.x) >> 5;
    int lane = threadIdx.x & 31;
    if (gw >= NB) return;
    const float* e = enc + (size_t)gw * 64;
    float x0 = e[lane], x1 = e[lane + 32];
    int d0 = (int)rintf(sigf(x0) * 10.0f);  // round-half-even, matches jnp.round
    int d1 = (int)rintf(sigf(x1) * 10.0f);
    float ent = 0.f;
#pragma unroll
    for (int b = 0; b < 11; b++) {
        int c = __popc(__ballot_sync(0xffffffffu, d0 == b)) +
                __popc(__ballot_sync(0xffffffffu, d1 == b));
        if (c > 0) {
            float p = c * (1.0f / 64.0f);
            ent -= p * logf(p + 1e-8f);
        }
    }
    if (lane == 0) {
        float eq = sigf(ent - 2.0f);
        float n  = g_norm[fi * NB + gw];
        float cq = (n > 0.01f) ? (1.0f / 768.0f) : 0.0f;
        float t  = n / fmaxf(n, 1e-12f);
        float dq = sigf(t * t - 0.5f);
        outrow[gw] = (eq + cq + dq) * (1.0f / 3.0f);
    }
}

// ---------------- overall (row 17) ----------------
__global__ void overall_k(float* __restrict__ out)
{
    int i = blockIdx.x * blockDim.x + threadIdx.x;
    if (i >= NB) return;
    float v = out[0 * NB + i] + out[1 * NB + i] + out[4 * NB + i] + out[5 * NB + i] +
              out[7 * NB + i] + 0.5f * (out[8 * NB + i] + out[9 * NB + i]);
    out[17 * NB + i] = v * (1.0f / 6.0f);
}

// ---------------- host ----------------
static inline void launch_gemm(const float* A1, const float* A2, int Khalf, int Ktot,
                               const float* W, int N, const float* bias, float* C, int act)
{
    dim3 grid(N / 64, NB / 128);
    gemm_k<<<grid, 256>>>(A1, A2 ? A2 : A1, Khalf, Ktot, W, N, bias, C, act);
}

extern "C" void kernel_launch(void* const* d_in, const int* in_sizes, int n_in,
                              void* d_out, int out_size)
{
    const float* img  = (const float*)d_in[0];
    const float* txt  = (const float*)d_in[1];
    const float* eimg = (const float*)d_in[2];
    const float* etxt = (const float*)d_in[3];
    // d_in[4] = missing_type (unused)
    const float* info_w1 = (const float*)d_in[5];
    const float* info_b1 = (const float*)d_in[6];
    const float* info_w2 = (const float*)d_in[7];
    const float* info_b2 = (const float*)d_in[8];
    const float* imp_w1  = (const float*)d_in[9];
    const float* imp_b1  = (const float*)d_in[10];
    const float* imp_w2  = (const float*)d_in[11];
    const float* imp_b2  = (const float*)d_in[12];
    const float* disc_w1 = (const float*)d_in[13];
    const float* disc_b1 = (const float*)d_in[14];
    const float* disc_w2 = (const float*)d_in[15];
    const float* disc_b2 = (const float*)d_in[16];
    const float* disc_w3 = (const float*)d_in[17];
    const float* disc_b3 = (const float*)d_in[18];
    const float* cons_w1 = (const float*)d_in[19];
    const float* cons_b1 = (const float*)d_in[20];
    const float* cons_w2 = (const float*)d_in[21];
    const float* cons_b2 = (const float*)d_in[22];
    const float* cons_w3 = (const float*)d_in[23];
    const float* cons_b3 = (const float*)d_in[24];
    const float* diff_w1 = (const float*)d_in[25];
    const float* diff_b1 = (const float*)d_in[26];
    const float* diff_w2 = (const float*)d_in[27];
    const float* diff_b2 = (const float*)d_in[28];
    const float* diff_w3 = (const float*)d_in[29];
    const float* diff_b3 = (const float*)d_in[30];

    float* out = (float*)d_out;

    float *scrA, *scrB, *scrC, *scrD;
    cudaGetSymbolAddress((void**)&scrA, g_scrA);
    cudaGetSymbolAddress((void**)&scrB, g_scrB);
    cudaGetSymbolAddress((void**)&scrC, g_scrC);
    cudaGetSymbolAddress((void**)&scrD, g_scrD);

    const int GELU = 1, LIN = 0;

    // geometric (rows 0..3) + norms for info
    rowstats_k<<<(4 * NB) / 8, 256>>>(img, txt, eimg, etxt, out);

    // information (rows 4,5)
    const float* infeats[2] = { img, txt };
    for (int i = 0; i < 2; i++) {
        launch_gemm(infeats[i], nullptr, 768, 768, info_w1, 256, info_b1, scrC, GELU);
        launch_gemm(scrC, nullptr, 256, 256, info_w2, 64, info_b2, scrD, LIN);
        info_final_k<<<NB / 8, 256>>>(scrD, i, out + (4 + i) * NB);
    }

    // importance (rows 8..11): img, txt, eimg, etxt
    const float* impfeats[4] = { img, txt, eimg, etxt };
    for (int i = 0; i < 4; i++) {
        launch_gemm(impfeats[i], nullptr, 768, 768, imp_w1, 384, imp_b1, scrB, GELU);
        dot_head_k<<<NB / 8, 256>>>(scrB, 384, imp_w2, imp_b2, out + (8 + i) * NB);
    }

    // discriminator (rows 12..15): img, eimg, txt, etxt
    const float* discfeats[4] = { img, eimg, txt, etxt };
    for (int i = 0; i < 4; i++) {
        launch_gemm(discfeats[i], nullptr, 768, 768, disc_w1, 256, disc_b1, scrC, GELU);
        launch_gemm(scrC, nullptr, 256, 256, disc_w2, 64, disc_b2, scrD, GELU);
        dot_head_k<<<NB / 8, 256>>>(scrD, 64, disc_w3, disc_b3, out + (12 + i) * NB);
    }

    // consistency original (row 6)
    launch_gemm(img, txt, 768, 1536, cons_w1, 768, cons_b1, scrA, GELU);
    launch_gemm(scrA, nullptr, 768, 768, cons_w2, 384, cons_b2, scrB, GELU);
    dot_head_k<<<NB / 8, 256>>>(scrB, 384, cons_w3, cons_b3, out + 6 * NB);

    // consistency enhanced (row 7)
    launch_gemm(eimg, etxt, 768, 1536, cons_w1, 768, cons_b1, scrA, GELU);
    launch_gemm(scrA, nullptr, 768, 768, cons_w2, 384, cons_b2, scrB, GELU);
    dot_head_k<<<NB / 8, 256>>>(scrB, 384, cons_w3, cons_b3, out + 7 * NB);

    // difficulty (row 16)
    launch_gemm(eimg, etxt, 768, 1536, diff_w1, 768, diff_b1, scrA, GELU);
    launch_gemm(scrA, nullptr, 768, 768, diff_w2, 384, diff_b2, scrB, GELU);
    dot_head_k<<<NB / 8, 256>>>(scrB, 384, diff_w3, diff_b3, out + 16 * NB);

    // overall (row 17)
    overall_k<<<NB / 256, 256>>>(out);
}